// round 8
// baseline (speedup 1.0000x reference)
#include <cuda_runtime.h>
#include <cuda_bf16.h>
#include <math.h>
#include <cstdint>

#define NN      16384
#define EE      262144
#define HID     128
#define NGAUSS  50
#define NINTER  6
#define NTAB    4096
#define DMAX    8.6610f
#define DELTA   (DMAX / (float)(NTAB - 1))
#define GSPACE  (10.0f / 49.0f)
#define GCOEFF  (-0.5f / (GSPACE * GSPACE))
#define LOG2F_C 0.69314718055994530942f
#define PI_O10  0.31415926535897932f

// ---------------- device scratch ----------------
__device__ float g_d[EE];
__device__ int   g_perm[EE];               // packed (t0 << 16) | src
__device__ float g_pw[EE];                 // lerp weight
__device__ int   g_start[NN + 1];
__device__ int   g_cnt[NN];
__device__ float g_h[NN * HID];            // fp32 residual stream
__device__ __nv_bfloat16 g_hb[NN * HID];   // bf16 shadow of h
__device__ __nv_bfloat16 g_xb[NN * HID];
__device__ __nv_bfloat16 g_aggb[NN * HID];
__device__ __nv_bfloat16 g_t1b[NN * HID];
__device__ __nv_bfloat16 g_Hb[NINTER * NTAB * HID];
__device__ __nv_bfloat16 g_Tb[NINTER * NTAB * HID];
__device__ float g_sum;

__device__ __forceinline__ float sspf(float x) {
    float sp = (x > 15.0f) ? x : log1pf(expf(x));
    return sp - LOG2F_C;
}

// ---------------- prep kernels ----------------
__global__ void zero_kernel() {
    int i = blockIdx.x * blockDim.x + threadIdx.x;
    if (i < NN) g_cnt[i] = 0;
    if (i == 0) g_sum = 0.0f;
}

__global__ void prep_kernel(const float* __restrict__ pos, const int* __restrict__ ei) {
    int e = blockIdx.x * blockDim.x + threadIdx.x;
    if (e >= EE) return;
    int s = ei[e];
    int t = ei[EE + e];
    float dx = pos[3 * s + 0] - pos[3 * t + 0];
    float dy = pos[3 * s + 1] - pos[3 * t + 1];
    float dz = pos[3 * s + 2] - pos[3 * t + 2];
    g_d[e] = sqrtf(dx * dx + dy * dy + dz * dz);
    atomicAdd(&g_cnt[t], 1);
}

__global__ void scan_kernel() {
    __shared__ int part[1024];
    int tid = threadIdx.x;
    int base = tid * 16;
    int loc[16];
    int s = 0;
#pragma unroll
    for (int i = 0; i < 16; i++) { loc[i] = g_cnt[base + i]; s += loc[i]; }
    part[tid] = s;
    __syncthreads();
    for (int off = 1; off < 1024; off <<= 1) {
        int v = part[tid];
        int add = (tid >= off) ? part[tid - off] : 0;
        __syncthreads();
        part[tid] = v + add;
        __syncthreads();
    }
    int excl = (tid == 0) ? 0 : part[tid - 1];
#pragma unroll
    for (int i = 0; i < 16; i++) {
        g_start[base + i] = excl;
        g_cnt[base + i] = excl;
        excl += loc[i];
    }
    if (tid == 1023) g_start[NN] = excl;
}

__global__ void scatter_kernel(const int* __restrict__ ei) {
    int e = blockIdx.x * blockDim.x + threadIdx.x;
    if (e >= EE) return;
    int t = ei[EE + e];
    int s = ei[e];
    float f = g_d[e] * (1.0f / DELTA);
    int t0 = (int)f;
    t0 = min(t0, NTAB - 2);
    float w = f - (float)t0;
    int p = atomicAdd(&g_cnt[t], 1);
    g_perm[p] = (t0 << 16) | s;
    g_pw[p] = w;
}

__global__ void emb_kernel(const int* __restrict__ z, const float* __restrict__ emb) {
    int idx = blockIdx.x * blockDim.x + threadIdx.x;
    if (idx >= NN * HID) return;
    int n = idx >> 7, c = idx & 127;
    float v = emb[z[n] * HID + c];
    g_h[idx] = v;
    g_hb[idx] = __float2bfloat16(v);
}

__global__ void tableH_kernel(const float* __restrict__ Wf1, const float* __restrict__ bf1) {
    int inter = blockIdx.y;
    int tbase = blockIdx.x * 8;
    __shared__ float W1s[NGAUSS * HID];
    __shared__ float eas[8][NGAUSS];
    const float* W1 = Wf1 + inter * NGAUSS * HID;
    for (int i = threadIdx.x; i < NGAUSS * HID; i += 128) W1s[i] = W1[i];
    for (int i = threadIdx.x; i < 8 * NGAUSS; i += 128) {
        int r = i / NGAUSS, k = i % NGAUSS;
        float dt = (tbase + r) * DELTA;
        float u = dt - k * GSPACE;
        eas[r][k] = expf(GCOEFF * u * u);
    }
    __syncthreads();
    float b = bf1[inter * HID + threadIdx.x];
#pragma unroll
    for (int r = 0; r < 8; r++) {
        float s = b;
#pragma unroll
        for (int k = 0; k < NGAUSS; k++) s += eas[r][k] * W1s[k * HID + threadIdx.x];
        g_Hb[(size_t)(inter * NTAB + tbase + r) * HID + threadIdx.x] = __float2bfloat16(sspf(s));
    }
}

// ---------------- MMA helpers ----------------
#define MMA16816(d, a, b0, b1) \
    asm volatile("mma.sync.aligned.m16n8k16.row.col.f32.bf16.bf16.f32 " \
        "{%0,%1,%2,%3}, {%4,%5,%6,%7}, {%8,%9}, {%0,%1,%2,%3};" \
        : "+f"((d)[0]), "+f"((d)[1]), "+f"((d)[2]), "+f"((d)[3]) \
        : "r"((a)[0]), "r"((a)[1]), "r"((a)[2]), "r"((a)[3]), "r"(b0), "r"(b1))

// ---------------- unified GEMM: C[Mx128] = A_bf16[Mx128] @ W_f32[128x128] ----------------
// W split hi/lo bf16 in smem (compensated); A bf16 (exact as stored).
#define MODE_PLAIN 0   // -> xb (bf16)
#define MODE_SSP   1   // ssp(. + bias) -> t1b (bf16)
#define MODE_RES   2   // h += . + bias (fp32) and hb (bf16)
#define MODE_FILT  3   // (. + bias) * C(row) -> table (bf16)

template <int MODE>
__global__ __launch_bounds__(256) void gemm_mma(
    const __nv_bfloat16* __restrict__ A, const float* __restrict__ W,
    const float* __restrict__ bias,
    float* __restrict__ hF, __nv_bfloat16* __restrict__ hB,
    __nv_bfloat16* __restrict__ outB,
    size_t aStride, size_t wStride, size_t bStride, size_t oStride)
{
    __shared__ __nv_bfloat16 sBhi[128][72];
    __shared__ __nv_bfloat16 sBlo[128][72];

    A += (size_t)blockIdx.y * aStride;
    W += (size_t)blockIdx.y * wStride;
    if (bias) bias += (size_t)blockIdx.y * bStride;
    if (outB) outB += (size_t)blockIdx.y * oStride;

    const int tid = threadIdx.x;
    const int w = tid >> 5, lane = tid & 31;
    const int wm = w >> 1, wn = w & 1;
    const int g = lane >> 2, tg = lane & 3;
    const int row0 = blockIdx.x * 128;

    float acc[2][8][4] = {};
    const __nv_bfloat16* aBase = A + (size_t)(row0 + wm * 32 + g) * 128;

    for (int kh = 0; kh < 2; kh++) {
        __syncthreads();
        for (int idx = tid; idx < 64 * 128; idx += 256) {
            int kp = idx >> 7, n = idx & 127;
            float v = W[(size_t)(kh * 64 + kp) * 128 + n];
            __nv_bfloat16 h = __float2bfloat16(v);
            sBhi[n][kp] = h;
            sBlo[n][kp] = __float2bfloat16(v - __bfloat162float(h));
        }
        __syncthreads();

#pragma unroll
        for (int ks = 0; ks < 4; ks++) {
            int kc = kh * 64 + ks * 16 + tg * 2;
            uint32_t af[2][4];
#pragma unroll
            for (int mt = 0; mt < 2; mt++) {
                const __nv_bfloat16* rp = aBase + (size_t)mt * 16 * 128;
                af[mt][0] = *(const uint32_t*)(rp + kc);
                af[mt][1] = *(const uint32_t*)(rp + 8 * 128 + kc);
                af[mt][2] = *(const uint32_t*)(rp + kc + 8);
                af[mt][3] = *(const uint32_t*)(rp + 8 * 128 + kc + 8);
            }
            int c = ks * 16 + tg * 2;
#pragma unroll
            for (int nt = 0; nt < 8; nt++) {
                int n = wn * 64 + nt * 8 + g;
                uint32_t bh0 = *(const uint32_t*)&sBhi[n][c];
                uint32_t bh1 = *(const uint32_t*)&sBhi[n][c + 8];
                uint32_t bl0 = *(const uint32_t*)&sBlo[n][c];
                uint32_t bl1 = *(const uint32_t*)&sBlo[n][c + 8];
#pragma unroll
                for (int mt = 0; mt < 2; mt++) {
                    MMA16816(acc[mt][nt], af[mt], bh0, bh1);
                    MMA16816(acc[mt][nt], af[mt], bl0, bl1);
                }
            }
        }
    }

    // ---- epilogue ----
#pragma unroll
    for (int mt = 0; mt < 2; mt++) {
        int r0 = row0 + wm * 32 + mt * 16 + g;
        int r1 = r0 + 8;
        float s0 = 1.0f, s1 = 1.0f;
        if (MODE == MODE_FILT) {
            s0 = 0.5f * (cosf((float)r0 * DELTA * PI_O10) + 1.0f);
            s1 = 0.5f * (cosf((float)r1 * DELTA * PI_O10) + 1.0f);
        }
#pragma unroll
        for (int nt = 0; nt < 8; nt++) {
            int cc = wn * 64 + nt * 8 + tg * 2;
            float vx0 = acc[mt][nt][0], vy0 = acc[mt][nt][1];
            float vx1 = acc[mt][nt][2], vy1 = acc[mt][nt][3];
            if (MODE != MODE_PLAIN) {
                float2 bv = *(const float2*)(bias + cc);
                vx0 += bv.x; vy0 += bv.y; vx1 += bv.x; vy1 += bv.y;
            }
            if (MODE == MODE_SSP) {
                vx0 = sspf(vx0); vy0 = sspf(vy0); vx1 = sspf(vx1); vy1 = sspf(vy1);
            }
            if (MODE == MODE_FILT) {
                vx0 *= s0; vy0 *= s0; vx1 *= s1; vy1 *= s1;
            }
            if (MODE == MODE_RES) {
                float* h0p = hF + (size_t)r0 * 128 + cc;
                float* h1p = hF + (size_t)r1 * 128 + cc;
                float2 e0 = *(const float2*)h0p;
                float2 e1 = *(const float2*)h1p;
                vx0 += e0.x; vy0 += e0.y; vx1 += e1.x; vy1 += e1.y;
                *(float2*)h0p = make_float2(vx0, vy0);
                *(float2*)h1p = make_float2(vx1, vy1);
                *(__nv_bfloat162*)(hB + (size_t)r0 * 128 + cc) = __floats2bfloat162_rn(vx0, vy0);
                *(__nv_bfloat162*)(hB + (size_t)r1 * 128 + cc) = __floats2bfloat162_rn(vx1, vy1);
            } else {
                *(__nv_bfloat162*)(outB + (size_t)r0 * 128 + cc) = __floats2bfloat162_rn(vx0, vy0);
                *(__nv_bfloat162*)(outB + (size_t)r1 * 128 + cc) = __floats2bfloat162_rn(vx1, vy1);
            }
        }
    }
}

// ---------------- edge aggregation (dst-sorted, warp/node, lerp table) ----------------
__device__ __forceinline__ void edge_acc(const __nv_bfloat16* xb, const __nv_bfloat16* Tb,
                                         int pk, float wt, int lane, float4& acc) {
    int s = pk & 0xFFFF;
    int t0 = pk >> 16;
    uint2 xv = ((const uint2*)(xb + (size_t)s * 128))[lane];
    uint2 a0 = ((const uint2*)(Tb + (size_t)t0 * 128))[lane];
    uint2 a1 = ((const uint2*)(Tb + (size_t)(t0 + 1) * 128))[lane];
    float2 x0 = __bfloat1622float2(*(__nv_bfloat162*)&xv.x);
    float2 x1 = __bfloat1622float2(*(__nv_bfloat162*)&xv.y);
    float2 p0 = __bfloat1622float2(*(__nv_bfloat162*)&a0.x);
    float2 p1 = __bfloat1622float2(*(__nv_bfloat162*)&a0.y);
    float2 q0 = __bfloat1622float2(*(__nv_bfloat162*)&a1.x);
    float2 q1 = __bfloat1622float2(*(__nv_bfloat162*)&a1.y);
    float w0 = 1.0f - wt;
    acc.x += x0.x * (w0 * p0.x + wt * q0.x);
    acc.y += x0.y * (w0 * p0.y + wt * q0.y);
    acc.z += x1.x * (w0 * p1.x + wt * q1.x);
    acc.w += x1.y * (w0 * p1.y + wt * q1.y);
}

__global__ void agg_kernel(const __nv_bfloat16* __restrict__ xb,
                           const __nv_bfloat16* __restrict__ Tb) {
    int warp = (blockIdx.x * blockDim.x + threadIdx.x) >> 5;
    int lane = threadIdx.x & 31;
    if (warp >= NN) return;
    int b = g_start[warp];
    int e = g_start[warp + 1];
    float4 acc = make_float4(0.f, 0.f, 0.f, 0.f);
    int j = b;
    for (; j + 2 <= e; j += 2) {
        int pk0 = g_perm[j], pk1 = g_perm[j + 1];
        float w0 = g_pw[j], w1 = g_pw[j + 1];
        edge_acc(xb, Tb, pk0, w0, lane, acc);
        edge_acc(xb, Tb, pk1, w1, lane, acc);
    }
    if (j < e) edge_acc(xb, Tb, g_perm[j], g_pw[j], lane, acc);
    __nv_bfloat162 o0 = __floats2bfloat162_rn(acc.x, acc.y);
    __nv_bfloat162 o1 = __floats2bfloat162_rn(acc.z, acc.w);
    uint2 ov;
    ov.x = *(uint32_t*)&o0;
    ov.y = *(uint32_t*)&o1;
    ((uint2*)(g_aggb + (size_t)warp * 128))[lane] = ov;
}

// ---------------- output head ----------------
__global__ void out_kernel(const float* __restrict__ Wo1, const float* __restrict__ bo1,
                           const float* __restrict__ Wo2) {
    int node = blockIdx.x * 4 + (threadIdx.x >> 6);
    int t = threadIdx.x & 63;
    const float* hr = g_h + (size_t)node * 128;
    float s = bo1[t];
#pragma unroll
    for (int k = 0; k < 128; k++) s += hr[k] * Wo1[k * 64 + t];
    float v = sspf(s) * Wo2[t];
#pragma unroll
    for (int off = 16; off > 0; off >>= 1)
        v += __shfl_xor_sync(0xFFFFFFFFu, v, off);
    if ((threadIdx.x & 31) == 0) atomicAdd(&g_sum, v);
}

__global__ void final_kernel(float* __restrict__ out, const float* __restrict__ bo2) {
    float v = g_sum + (float)NN * bo2[0];
    out[0] = fmaxf(v, 0.0f);
}

// ---------------- launch ----------------
extern "C" void kernel_launch(void* const* d_in, const int* in_sizes, int n_in,
                              void* d_out, int out_size) {
    const int*   z    = (const int*)d_in[0];
    const float* pos  = (const float*)d_in[1];
    const int*   ei   = (const int*)d_in[2];
    const float* emb  = (const float*)d_in[3];
    const float* Wf1  = (const float*)d_in[4];
    const float* bf1  = (const float*)d_in[5];
    const float* Wf2  = (const float*)d_in[6];
    const float* bf2  = (const float*)d_in[7];
    const float* Wl1  = (const float*)d_in[8];
    const float* Wl2  = (const float*)d_in[9];
    const float* bl2  = (const float*)d_in[10];
    const float* Wl   = (const float*)d_in[11];
    const float* bl   = (const float*)d_in[12];
    const float* Wo1  = (const float*)d_in[13];
    const float* bo1  = (const float*)d_in[14];
    const float* Wo2  = (const float*)d_in[15];
    const float* bo2  = (const float*)d_in[16];
    float* out = (float*)d_out;

    float *p_h;
    __nv_bfloat16 *p_hb, *p_xb, *p_aggb, *p_t1b, *p_Hb, *p_Tb;
    cudaGetSymbolAddress((void**)&p_h,    g_h);
    cudaGetSymbolAddress((void**)&p_hb,   g_hb);
    cudaGetSymbolAddress((void**)&p_xb,   g_xb);
    cudaGetSymbolAddress((void**)&p_aggb, g_aggb);
    cudaGetSymbolAddress((void**)&p_t1b,  g_t1b);
    cudaGetSymbolAddress((void**)&p_Hb,   g_Hb);
    cudaGetSymbolAddress((void**)&p_Tb,   g_Tb);

    // --- edge prep + dst sort ---
    zero_kernel<<<NN / 256, 256>>>();
    prep_kernel<<<EE / 256, 256>>>(pos, ei);
    scan_kernel<<<1, 1024>>>();
    scatter_kernel<<<EE / 256, 256>>>(ei);
    emb_kernel<<<NN * HID / 256, 256>>>(z, emb);

    // --- filter tables (batched over all 6 interactions) ---
    tableH_kernel<<<dim3(NTAB / 8, NINTER), 128>>>(Wf1, bf1);
    gemm_mma<MODE_FILT><<<dim3(NTAB / 128, NINTER), 256>>>(
        p_Hb, Wf2, bf2, nullptr, nullptr, p_Tb,
        (size_t)NTAB * HID, (size_t)HID * HID, (size_t)HID, (size_t)NTAB * HID);

    // --- interaction blocks ---
    for (int i = 0; i < NINTER; i++) {
        gemm_mma<MODE_PLAIN><<<NN / 128, 256>>>(
            p_hb, Wl1 + (size_t)i * HID * HID, nullptr, nullptr, nullptr, p_xb, 0, 0, 0, 0);
        agg_kernel<<<NN / 8, 256>>>(p_xb, p_Tb + (size_t)i * NTAB * HID);
        gemm_mma<MODE_SSP><<<NN / 128, 256>>>(
            p_aggb, Wl2 + (size_t)i * HID * HID, bl2 + (size_t)i * HID,
            nullptr, nullptr, p_t1b, 0, 0, 0, 0);
        gemm_mma<MODE_RES><<<NN / 128, 256>>>(
            p_t1b, Wl + (size_t)i * HID * HID, bl + (size_t)i * HID,
            p_h, p_hb, nullptr, 0, 0, 0, 0);
    }

    // --- readout ---
    out_kernel<<<NN / 4, 256>>>(Wo1, bo1, Wo2);
    final_kernel<<<1, 1>>>(out, bo2);
}

// round 9
// speedup vs baseline: 1.3454x; 1.3454x over previous
#include <cuda_runtime.h>
#include <cuda_bf16.h>
#include <math.h>
#include <cstdint>

#define NN      16384
#define EE      262144
#define HID     128
#define NGAUSS  50
#define NINTER  6
#define NTAB    4096
#define DMAX    8.6610f
#define DELTA   (DMAX / (float)(NTAB - 1))
#define GSPACE  (10.0f / 49.0f)
#define GCOEFF  (-0.5f / (GSPACE * GSPACE))
#define LOG2F_C 0.69314718055994530942f
#define PI_O10  0.31415926535897932f

// ---------------- device scratch ----------------
__device__ float g_d[EE];
__device__ int   g_perm[EE];               // packed (t0 << 16) | src
__device__ float g_pw[EE];                 // lerp weight
__device__ int   g_start[NN + 1];
__device__ int   g_cnt[NN];
__device__ float g_h[NN * HID];            // fp32 residual stream
__device__ __nv_bfloat16 g_hb[NN * HID];   // bf16 shadow (only for first x GEMM)
__device__ __nv_bfloat16 g_xb[NN * HID];
__device__ __nv_bfloat16 g_aggb[NN * HID];
__device__ __nv_bfloat16 g_Hb[NINTER * NTAB * HID];
__device__ __nv_bfloat16 g_Tb[NINTER * NTAB * HID];
__device__ float g_sum;

__device__ __forceinline__ float sspf(float x) {
    float sp = (x > 15.0f) ? x : log1pf(expf(x));
    return sp - LOG2F_C;
}

// ---------------- prep kernels ----------------
__global__ void zero_kernel() {
    int i = blockIdx.x * blockDim.x + threadIdx.x;
    if (i < NN) g_cnt[i] = 0;
    if (i == 0) g_sum = 0.0f;
}

__global__ void prep_kernel(const float* __restrict__ pos, const int* __restrict__ ei) {
    int e = blockIdx.x * blockDim.x + threadIdx.x;
    if (e >= EE) return;
    int s = ei[e];
    int t = ei[EE + e];
    float dx = pos[3 * s + 0] - pos[3 * t + 0];
    float dy = pos[3 * s + 1] - pos[3 * t + 1];
    float dz = pos[3 * s + 2] - pos[3 * t + 2];
    g_d[e] = sqrtf(dx * dx + dy * dy + dz * dz);
    atomicAdd(&g_cnt[t], 1);
}

__global__ void scan_kernel() {
    __shared__ int part[1024];
    int tid = threadIdx.x;
    int base = tid * 16;
    int loc[16];
    int s = 0;
#pragma unroll
    for (int i = 0; i < 16; i++) { loc[i] = g_cnt[base + i]; s += loc[i]; }
    part[tid] = s;
    __syncthreads();
    for (int off = 1; off < 1024; off <<= 1) {
        int v = part[tid];
        int add = (tid >= off) ? part[tid - off] : 0;
        __syncthreads();
        part[tid] = v + add;
        __syncthreads();
    }
    int excl = (tid == 0) ? 0 : part[tid - 1];
#pragma unroll
    for (int i = 0; i < 16; i++) {
        g_start[base + i] = excl;
        g_cnt[base + i] = excl;
        excl += loc[i];
    }
    if (tid == 1023) g_start[NN] = excl;
}

__global__ void scatter_kernel(const int* __restrict__ ei) {
    int e = blockIdx.x * blockDim.x + threadIdx.x;
    if (e >= EE) return;
    int t = ei[EE + e];
    int s = ei[e];
    float f = g_d[e] * (1.0f / DELTA);
    int t0 = (int)f;
    t0 = min(t0, NTAB - 2);
    float w = f - (float)t0;
    int p = atomicAdd(&g_cnt[t], 1);
    g_perm[p] = (t0 << 16) | s;
    g_pw[p] = w;
}

__global__ void emb_kernel(const int* __restrict__ z, const float* __restrict__ emb) {
    int idx = blockIdx.x * blockDim.x + threadIdx.x;
    if (idx >= NN * HID) return;
    int n = idx >> 7, c = idx & 127;
    float v = emb[z[n] * HID + c];
    g_h[idx] = v;
    g_hb[idx] = __float2bfloat16(v);
}

__global__ void tableH_kernel(const float* __restrict__ Wf1, const float* __restrict__ bf1) {
    int inter = blockIdx.y;
    int tbase = blockIdx.x * 8;
    __shared__ float W1s[NGAUSS * HID];
    __shared__ float eas[8][NGAUSS];
    const float* W1 = Wf1 + inter * NGAUSS * HID;
    for (int i = threadIdx.x; i < NGAUSS * HID; i += 128) W1s[i] = W1[i];
    for (int i = threadIdx.x; i < 8 * NGAUSS; i += 128) {
        int r = i / NGAUSS, k = i % NGAUSS;
        float dt = (tbase + r) * DELTA;
        float u = dt - k * GSPACE;
        eas[r][k] = expf(GCOEFF * u * u);
    }
    __syncthreads();
    float b = bf1[inter * HID + threadIdx.x];
#pragma unroll
    for (int r = 0; r < 8; r++) {
        float s = b;
#pragma unroll
        for (int k = 0; k < NGAUSS; k++) s += eas[r][k] * W1s[k * HID + threadIdx.x];
        g_Hb[(size_t)(inter * NTAB + tbase + r) * HID + threadIdx.x] = __float2bfloat16(sspf(s));
    }
}

// ---------------- MMA helpers ----------------
#define MMA16816(d, a, b0, b1) \
    asm volatile("mma.sync.aligned.m16n8k16.row.col.f32.bf16.bf16.f32 " \
        "{%0,%1,%2,%3}, {%4,%5,%6,%7}, {%8,%9}, {%0,%1,%2,%3};" \
        : "+f"((d)[0]), "+f"((d)[1]), "+f"((d)[2]), "+f"((d)[3]) \
        : "r"((a)[0]), "r"((a)[1]), "r"((a)[2]), "r"((a)[3]), "r"(b0), "r"(b1))

// ---------------- standalone GEMM (first x, filter tables) ----------------
#define MODE_PLAIN 0
#define MODE_FILT  3

template <int MODE>
__global__ __launch_bounds__(256) void gemm_mma(
    const __nv_bfloat16* __restrict__ A, const float* __restrict__ W,
    const float* __restrict__ bias,
    __nv_bfloat16* __restrict__ outB,
    size_t aStride, size_t wStride, size_t bStride, size_t oStride)
{
    __shared__ __nv_bfloat16 sBhi[128][72];
    __shared__ __nv_bfloat16 sBlo[128][72];

    A += (size_t)blockIdx.y * aStride;
    W += (size_t)blockIdx.y * wStride;
    if (bias) bias += (size_t)blockIdx.y * bStride;
    outB += (size_t)blockIdx.y * oStride;

    const int tid = threadIdx.x;
    const int w = tid >> 5, lane = tid & 31;
    const int wm = w >> 1, wn = w & 1;
    const int g = lane >> 2, tg = lane & 3;
    const int row0 = blockIdx.x * 128;

    float acc[2][8][4] = {};
    const __nv_bfloat16* aBase = A + (size_t)(row0 + wm * 32 + g) * 128;

    for (int kh = 0; kh < 2; kh++) {
        __syncthreads();
        for (int idx = tid; idx < 64 * 128; idx += 256) {
            int kp = idx >> 7, n = idx & 127;
            float v = W[(size_t)(kh * 64 + kp) * 128 + n];
            __nv_bfloat16 h = __float2bfloat16(v);
            sBhi[n][kp] = h;
            sBlo[n][kp] = __float2bfloat16(v - __bfloat162float(h));
        }
        __syncthreads();

#pragma unroll
        for (int ks = 0; ks < 4; ks++) {
            int kc = kh * 64 + ks * 16 + tg * 2;
            uint32_t af[2][4];
#pragma unroll
            for (int mt = 0; mt < 2; mt++) {
                const __nv_bfloat16* rp = aBase + (size_t)mt * 16 * 128;
                af[mt][0] = *(const uint32_t*)(rp + kc);
                af[mt][1] = *(const uint32_t*)(rp + 8 * 128 + kc);
                af[mt][2] = *(const uint32_t*)(rp + kc + 8);
                af[mt][3] = *(const uint32_t*)(rp + 8 * 128 + kc + 8);
            }
            int c = ks * 16 + tg * 2;
#pragma unroll
            for (int nt = 0; nt < 8; nt++) {
                int n = wn * 64 + nt * 8 + g;
                uint32_t bh0 = *(const uint32_t*)&sBhi[n][c];
                uint32_t bh1 = *(const uint32_t*)&sBhi[n][c + 8];
                uint32_t bl0 = *(const uint32_t*)&sBlo[n][c];
                uint32_t bl1 = *(const uint32_t*)&sBlo[n][c + 8];
#pragma unroll
                for (int mt = 0; mt < 2; mt++) {
                    MMA16816(acc[mt][nt], af[mt], bh0, bh1);
                    MMA16816(acc[mt][nt], af[mt], bl0, bl1);
                }
            }
        }
    }

#pragma unroll
    for (int mt = 0; mt < 2; mt++) {
        int r0 = row0 + wm * 32 + mt * 16 + g;
        int r1 = r0 + 8;
        float s0 = 1.0f, s1 = 1.0f;
        if (MODE == MODE_FILT) {
            s0 = 0.5f * (cosf((float)r0 * DELTA * PI_O10) + 1.0f);
            s1 = 0.5f * (cosf((float)r1 * DELTA * PI_O10) + 1.0f);
        }
#pragma unroll
        for (int nt = 0; nt < 8; nt++) {
            int cc = wn * 64 + nt * 8 + tg * 2;
            float vx0 = acc[mt][nt][0], vy0 = acc[mt][nt][1];
            float vx1 = acc[mt][nt][2], vy1 = acc[mt][nt][3];
            if (MODE == MODE_FILT) {
                float2 bv = *(const float2*)(bias + cc);
                vx0 = (vx0 + bv.x) * s0; vy0 = (vy0 + bv.y) * s0;
                vx1 = (vx1 + bv.x) * s1; vy1 = (vy1 + bv.y) * s1;
            }
            *(__nv_bfloat162*)(outB + (size_t)r0 * 128 + cc) = __floats2bfloat162_rn(vx0, vy0);
            *(__nv_bfloat162*)(outB + (size_t)r1 * 128 + cc) = __floats2bfloat162_rn(vx1, vy1);
        }
    }
}

// ---------------- fused 3-GEMM stage helper ----------------
// acc[2][NT][4] += A[rows of this warp] @ W (hi+lo compensated).
// A: bf16, row stride lda (global or shared). W: fp32 [128..][LDW] global, staged into sWhi/sWlo.
template <int NT, int LDW>
__device__ __forceinline__ void mma_stage(
    const __nv_bfloat16* __restrict__ A, int lda,
    const float* __restrict__ W,
    __nv_bfloat16* sWhi, __nv_bfloat16* sWlo,
    int tid, int wm, int wn, int g, int tg,
    float acc[2][NT][4])
{
    const int colbase = wn * (NT * 8);
    const __nv_bfloat16* rp0 = A + (wm * 32 + g) * lda;
    for (int kh = 0; kh < 2; kh++) {
        __syncthreads();
        for (int idx = tid; idx < 64 * LDW; idx += 256) {
            int kp = idx / LDW, n = idx % LDW;
            float v = W[(size_t)(kh * 64 + kp) * LDW + n];
            __nv_bfloat16 h = __float2bfloat16(v);
            sWhi[n * 72 + kp] = h;
            sWlo[n * 72 + kp] = __float2bfloat16(v - __bfloat162float(h));
        }
        __syncthreads();
#pragma unroll
        for (int ks = 0; ks < 4; ks++) {
            int kc = kh * 64 + ks * 16 + tg * 2;
            uint32_t af[2][4];
#pragma unroll
            for (int mt = 0; mt < 2; mt++) {
                const __nv_bfloat16* rp = rp0 + mt * 16 * lda;
                af[mt][0] = *(const uint32_t*)(rp + kc);
                af[mt][1] = *(const uint32_t*)(rp + 8 * lda + kc);
                af[mt][2] = *(const uint32_t*)(rp + kc + 8);
                af[mt][3] = *(const uint32_t*)(rp + 8 * lda + kc + 8);
            }
            int c = ks * 16 + tg * 2;
#pragma unroll
            for (int nt = 0; nt < NT; nt++) {
                int n = colbase + nt * 8 + g;
                uint32_t bh0 = *(const uint32_t*)(sWhi + n * 72 + c);
                uint32_t bh1 = *(const uint32_t*)(sWhi + n * 72 + c + 8);
                uint32_t bl0 = *(const uint32_t*)(sWlo + n * 72 + c);
                uint32_t bl1 = *(const uint32_t*)(sWlo + n * 72 + c + 8);
#pragma unroll
                for (int mt = 0; mt < 2; mt++) {
                    MMA16816(acc[mt][nt], af[mt], bh0, bh1);
                    MMA16816(acc[mt][nt], af[mt], bl0, bl1);
                }
            }
        }
    }
}

// ---------------- fused interaction update: 3 chained GEMMs, smem staging ----------------
// t  = ssp(aggb @ Wl2 + bl2)            (smem bf16)
// hn = t @ Wl + bl + h  -> h (fp32)     (smem bf16)
// LAST=0: xb = hn @ W3 (Wl1_next)
// LAST=1: g_sum += sum ssp(hn @ Wo1 + bo1) . Wo2
template <bool LAST>
__global__ __launch_bounds__(256) void fused_update(
    const __nv_bfloat16* __restrict__ aggb,
    float* __restrict__ h,
    const float* __restrict__ Wl2, const float* __restrict__ bl2,
    const float* __restrict__ Wl,  const float* __restrict__ bl,
    const float* __restrict__ W3,
    const float* __restrict__ bo1, const float* __restrict__ Wo2,
    __nv_bfloat16* __restrict__ xb)
{
    extern __shared__ __align__(16) char smem_raw[];
    __nv_bfloat16* sWhi = (__nv_bfloat16*)smem_raw;            // 128*72
    __nv_bfloat16* sWlo = sWhi + 128 * 72;                     // 128*72
    __nv_bfloat16* sT   = sWlo + 128 * 72;                     // 128*136
    __nv_bfloat16* sHn  = sT + 128 * 136;                      // 128*136

    const int tid = threadIdx.x;
    const int w = tid >> 5, lane = tid & 31;
    const int wm = w >> 1, wn = w & 1;
    const int g = lane >> 2, tg = lane & 3;
    const int row0 = blockIdx.x * 128;

    // ---- stage 1: t = ssp(aggb @ Wl2 + bl2) -> sT ----
    {
        float acc[2][8][4] = {};
        mma_stage<8, 128>(aggb + (size_t)row0 * 128, 128, Wl2, sWhi, sWlo,
                          tid, wm, wn, g, tg, acc);
#pragma unroll
        for (int mt = 0; mt < 2; mt++) {
            int r0 = wm * 32 + mt * 16 + g;
            int r1 = r0 + 8;
#pragma unroll
            for (int nt = 0; nt < 8; nt++) {
                int cc = wn * 64 + nt * 8 + tg * 2;
                float2 bv = *(const float2*)(bl2 + cc);
                float vx0 = sspf(acc[mt][nt][0] + bv.x);
                float vy0 = sspf(acc[mt][nt][1] + bv.y);
                float vx1 = sspf(acc[mt][nt][2] + bv.x);
                float vy1 = sspf(acc[mt][nt][3] + bv.y);
                *(__nv_bfloat162*)(sT + r0 * 136 + cc) = __floats2bfloat162_rn(vx0, vy0);
                *(__nv_bfloat162*)(sT + r1 * 136 + cc) = __floats2bfloat162_rn(vx1, vy1);
            }
        }
    }
    // (sync inside next mma_stage orders sT writes before reads)

    // ---- stage 2: hn = t @ Wl + bl + h -> h (fp32) + sHn (bf16) ----
    {
        float acc[2][8][4] = {};
        mma_stage<8, 128>(sT, 136, Wl, sWhi, sWlo, tid, wm, wn, g, tg, acc);
#pragma unroll
        for (int mt = 0; mt < 2; mt++) {
            int r0 = wm * 32 + mt * 16 + g;
            int r1 = r0 + 8;
            float* h0p = h + (size_t)(row0 + r0) * 128;
            float* h1p = h + (size_t)(row0 + r1) * 128;
#pragma unroll
            for (int nt = 0; nt < 8; nt++) {
                int cc = wn * 64 + nt * 8 + tg * 2;
                float2 bv = *(const float2*)(bl + cc);
                float2 e0 = *(const float2*)(h0p + cc);
                float2 e1 = *(const float2*)(h1p + cc);
                float vx0 = acc[mt][nt][0] + bv.x + e0.x;
                float vy0 = acc[mt][nt][1] + bv.y + e0.y;
                float vx1 = acc[mt][nt][2] + bv.x + e1.x;
                float vy1 = acc[mt][nt][3] + bv.y + e1.y;
                *(float2*)(h0p + cc) = make_float2(vx0, vy0);
                *(float2*)(h1p + cc) = make_float2(vx1, vy1);
                *(__nv_bfloat162*)(sHn + r0 * 136 + cc) = __floats2bfloat162_rn(vx0, vy0);
                *(__nv_bfloat162*)(sHn + r1 * 136 + cc) = __floats2bfloat162_rn(vx1, vy1);
            }
        }
    }

    // ---- stage 3: next x or readout ----
    if (!LAST) {
        float acc[2][8][4] = {};
        mma_stage<8, 128>(sHn, 136, W3, sWhi, sWlo, tid, wm, wn, g, tg, acc);
#pragma unroll
        for (int mt = 0; mt < 2; mt++) {
            int r0 = row0 + wm * 32 + mt * 16 + g;
            int r1 = r0 + 8;
#pragma unroll
            for (int nt = 0; nt < 8; nt++) {
                int cc = wn * 64 + nt * 8 + tg * 2;
                *(__nv_bfloat162*)(xb + (size_t)r0 * 128 + cc) =
                    __floats2bfloat162_rn(acc[mt][nt][0], acc[mt][nt][1]);
                *(__nv_bfloat162*)(xb + (size_t)r1 * 128 + cc) =
                    __floats2bfloat162_rn(acc[mt][nt][2], acc[mt][nt][3]);
            }
        }
    } else {
        float acc[2][4][4] = {};
        mma_stage<4, 64>(sHn, 136, W3, sWhi, sWlo, tid, wm, wn, g, tg, acc);
        float v = 0.0f;
#pragma unroll
        for (int mt = 0; mt < 2; mt++) {
#pragma unroll
            for (int nt = 0; nt < 4; nt++) {
                int cc = wn * 32 + nt * 8 + tg * 2;
                float2 bo = *(const float2*)(bo1 + cc);
                float2 w2 = *(const float2*)(Wo2 + cc);
                v += sspf(acc[mt][nt][0] + bo.x) * w2.x + sspf(acc[mt][nt][1] + bo.y) * w2.y;
                v += sspf(acc[mt][nt][2] + bo.x) * w2.x + sspf(acc[mt][nt][3] + bo.y) * w2.y;
            }
        }
#pragma unroll
        for (int off = 16; off > 0; off >>= 1)
            v += __shfl_xor_sync(0xFFFFFFFFu, v, off);
        if (lane == 0) atomicAdd(&g_sum, v);
    }
}

// ---------------- edge aggregation (dst-sorted, warp/node, lerp table) ----------------
__device__ __forceinline__ void edge_acc(const __nv_bfloat16* xb, const __nv_bfloat16* Tb,
                                         int pk, float wt, int lane, float4& acc) {
    int s = pk & 0xFFFF;
    int t0 = pk >> 16;
    uint2 xv = ((const uint2*)(xb + (size_t)s * 128))[lane];
    uint2 a0 = ((const uint2*)(Tb + (size_t)t0 * 128))[lane];
    uint2 a1 = ((const uint2*)(Tb + (size_t)(t0 + 1) * 128))[lane];
    float2 x0 = __bfloat1622float2(*(__nv_bfloat162*)&xv.x);
    float2 x1 = __bfloat1622float2(*(__nv_bfloat162*)&xv.y);
    float2 p0 = __bfloat1622float2(*(__nv_bfloat162*)&a0.x);
    float2 p1 = __bfloat1622float2(*(__nv_bfloat162*)&a0.y);
    float2 q0 = __bfloat1622float2(*(__nv_bfloat162*)&a1.x);
    float2 q1 = __bfloat1622float2(*(__nv_bfloat162*)&a1.y);
    float w0 = 1.0f - wt;
    acc.x += x0.x * (w0 * p0.x + wt * q0.x);
    acc.y += x0.y * (w0 * p0.y + wt * q0.y);
    acc.z += x1.x * (w0 * p1.x + wt * q1.x);
    acc.w += x1.y * (w0 * p1.y + wt * q1.y);
}

__global__ void agg_kernel(const __nv_bfloat16* __restrict__ xb,
                           const __nv_bfloat16* __restrict__ Tb) {
    int warp = (blockIdx.x * blockDim.x + threadIdx.x) >> 5;
    int lane = threadIdx.x & 31;
    if (warp >= NN) return;
    int b = g_start[warp];
    int e = g_start[warp + 1];
    float4 acc = make_float4(0.f, 0.f, 0.f, 0.f);
    int j = b;
    for (; j + 2 <= e; j += 2) {
        int pk0 = g_perm[j], pk1 = g_perm[j + 1];
        float w0 = g_pw[j], w1 = g_pw[j + 1];
        edge_acc(xb, Tb, pk0, w0, lane, acc);
        edge_acc(xb, Tb, pk1, w1, lane, acc);
    }
    if (j < e) edge_acc(xb, Tb, g_perm[j], g_pw[j], lane, acc);
    __nv_bfloat162 o0 = __floats2bfloat162_rn(acc.x, acc.y);
    __nv_bfloat162 o1 = __floats2bfloat162_rn(acc.z, acc.w);
    uint2 ov;
    ov.x = *(uint32_t*)&o0;
    ov.y = *(uint32_t*)&o1;
    ((uint2*)(g_aggb + (size_t)warp * 128))[lane] = ov;
}

__global__ void final_kernel(float* __restrict__ out, const float* __restrict__ bo2) {
    float v = g_sum + (float)NN * bo2[0];
    out[0] = fmaxf(v, 0.0f);
}

// ---------------- launch ----------------
extern "C" void kernel_launch(void* const* d_in, const int* in_sizes, int n_in,
                              void* d_out, int out_size) {
    const int*   z    = (const int*)d_in[0];
    const float* pos  = (const float*)d_in[1];
    const int*   ei   = (const int*)d_in[2];
    const float* emb  = (const float*)d_in[3];
    const float* Wf1  = (const float*)d_in[4];
    const float* bf1  = (const float*)d_in[5];
    const float* Wf2  = (const float*)d_in[6];
    const float* bf2  = (const float*)d_in[7];
    const float* Wl1  = (const float*)d_in[8];
    const float* Wl2  = (const float*)d_in[9];
    const float* bl2  = (const float*)d_in[10];
    const float* Wl   = (const float*)d_in[11];
    const float* bl   = (const float*)d_in[12];
    const float* Wo1  = (const float*)d_in[13];
    const float* bo1  = (const float*)d_in[14];
    const float* Wo2  = (const float*)d_in[15];
    const float* bo2  = (const float*)d_in[16];
    float* out = (float*)d_out;

    float *p_h;
    __nv_bfloat16 *p_hb, *p_xb, *p_aggb, *p_Hb, *p_Tb;
    cudaGetSymbolAddress((void**)&p_h,    g_h);
    cudaGetSymbolAddress((void**)&p_hb,   g_hb);
    cudaGetSymbolAddress((void**)&p_xb,   g_xb);
    cudaGetSymbolAddress((void**)&p_aggb, g_aggb);
    cudaGetSymbolAddress((void**)&p_Hb,   g_Hb);
    cudaGetSymbolAddress((void**)&p_Tb,   g_Tb);

    const int FUSED_SMEM = (2 * 128 * 72 + 2 * 128 * 136) * (int)sizeof(__nv_bfloat16);
    cudaFuncSetAttribute(fused_update<false>, cudaFuncAttributeMaxDynamicSharedMemorySize, FUSED_SMEM);
    cudaFuncSetAttribute(fused_update<true>,  cudaFuncAttributeMaxDynamicSharedMemorySize, FUSED_SMEM);

    // --- edge prep + dst sort ---
    zero_kernel<<<NN / 256, 256>>>();
    prep_kernel<<<EE / 256, 256>>>(pos, ei);
    scan_kernel<<<1, 1024>>>();
    scatter_kernel<<<EE / 256, 256>>>(ei);
    emb_kernel<<<NN * HID / 256, 256>>>(z, emb);

    // --- filter tables (batched over all 6 interactions) ---
    tableH_kernel<<<dim3(NTAB / 8, NINTER), 128>>>(Wf1, bf1);
    gemm_mma<MODE_FILT><<<dim3(NTAB / 128, NINTER), 256>>>(
        p_Hb, Wf2, bf2, p_Tb,
        (size_t)NTAB * HID, (size_t)HID * HID, (size_t)HID, (size_t)NTAB * HID);

    // --- first x = h @ Wl1[0] ---
    gemm_mma<MODE_PLAIN><<<NN / 128, 256>>>(p_hb, Wl1, nullptr, p_xb, 0, 0, 0, 0);

    // --- interaction blocks: agg + fused 3-GEMM update ---
    for (int i = 0; i < NINTER; i++) {
        agg_kernel<<<NN / 8, 256>>>(p_xb, p_Tb + (size_t)i * NTAB * HID);
        if (i < NINTER - 1) {
            fused_update<false><<<NN / 128, 256, FUSED_SMEM>>>(
                p_aggb, p_h,
                Wl2 + (size_t)i * HID * HID, bl2 + (size_t)i * HID,
                Wl  + (size_t)i * HID * HID, bl  + (size_t)i * HID,
                Wl1 + (size_t)(i + 1) * HID * HID, nullptr, nullptr, p_xb);
        } else {
            fused_update<true><<<NN / 128, 256, FUSED_SMEM>>>(
                p_aggb, p_h,
                Wl2 + (size_t)i * HID * HID, bl2 + (size_t)i * HID,
                Wl  + (size_t)i * HID * HID, bl  + (size_t)i * HID,
                Wo1, bo1, Wo2, nullptr);
        }
    }

    final_kernel<<<1, 1>>>(out, bo2);
}

// round 10
// speedup vs baseline: 1.4189x; 1.0546x over previous
#include <cuda_runtime.h>
#include <cuda_bf16.h>
#include <math.h>
#include <cstdint>

#define NN      16384
#define EE      262144
#define HID     128
#define NGAUSS  50
#define NINTER  6
#define NTAB    4096
#define DMAX    8.6610f
#define DELTA   (DMAX / (float)(NTAB - 1))
#define GSPACE  (10.0f / 49.0f)
#define GCOEFF  (-0.5f / (GSPACE * GSPACE))
#define LOG2F_C 0.69314718055994530942f
#define PI_O10  0.31415926535897932f

// ---------------- device scratch ----------------
__device__ float g_d[EE];
__device__ int   g_perm[EE];               // packed (t0 << 16) | src
__device__ float g_pw[EE];                 // lerp weight
__device__ int   g_start[NN + 1];
__device__ int   g_cnt[NN];
__device__ float g_h[NN * HID];            // fp32 residual stream
__device__ __nv_bfloat16 g_hb[NN * HID];   // bf16 shadow (first x GEMM)
__device__ __nv_bfloat16 g_xb[NN * HID];
__device__ __nv_bfloat16 g_aggb[NN * HID];
__device__ __nv_bfloat16 g_Hb[NINTER * NTAB * HID];
__device__ __nv_bfloat16 g_Tb[NINTER * NTAB * HID];
__device__ float g_sum;

__device__ __forceinline__ float sspf(float x) {
    float sp = (x > 15.0f) ? x : log1pf(expf(x));
    return sp - LOG2F_C;
}

// ---------------- prep kernels ----------------
__global__ void zero_kernel() {
    int i = blockIdx.x * blockDim.x + threadIdx.x;
    if (i < NN) g_cnt[i] = 0;
    if (i == 0) g_sum = 0.0f;
}

__global__ void prep_kernel(const float* __restrict__ pos, const int* __restrict__ ei) {
    int e = blockIdx.x * blockDim.x + threadIdx.x;
    if (e >= EE) return;
    int s = ei[e];
    int t = ei[EE + e];
    float dx = pos[3 * s + 0] - pos[3 * t + 0];
    float dy = pos[3 * s + 1] - pos[3 * t + 1];
    float dz = pos[3 * s + 2] - pos[3 * t + 2];
    g_d[e] = sqrtf(dx * dx + dy * dy + dz * dz);
    atomicAdd(&g_cnt[t], 1);
}

__global__ void scan_kernel() {
    __shared__ int part[1024];
    int tid = threadIdx.x;
    int base = tid * 16;
    int loc[16];
    int s = 0;
#pragma unroll
    for (int i = 0; i < 16; i++) { loc[i] = g_cnt[base + i]; s += loc[i]; }
    part[tid] = s;
    __syncthreads();
    for (int off = 1; off < 1024; off <<= 1) {
        int v = part[tid];
        int add = (tid >= off) ? part[tid - off] : 0;
        __syncthreads();
        part[tid] = v + add;
        __syncthreads();
    }
    int excl = (tid == 0) ? 0 : part[tid - 1];
#pragma unroll
    for (int i = 0; i < 16; i++) {
        g_start[base + i] = excl;
        g_cnt[base + i] = excl;
        excl += loc[i];
    }
    if (tid == 1023) g_start[NN] = excl;
}

__global__ void scatter_kernel(const int* __restrict__ ei) {
    int e = blockIdx.x * blockDim.x + threadIdx.x;
    if (e >= EE) return;
    int t = ei[EE + e];
    int s = ei[e];
    float f = g_d[e] * (1.0f / DELTA);
    int t0 = (int)f;
    t0 = min(t0, NTAB - 2);
    float w = f - (float)t0;
    int p = atomicAdd(&g_cnt[t], 1);
    g_perm[p] = (t0 << 16) | s;
    g_pw[p] = w;
}

__global__ void emb_kernel(const int* __restrict__ z, const float* __restrict__ emb) {
    int idx = blockIdx.x * blockDim.x + threadIdx.x;
    if (idx >= NN * HID) return;
    int n = idx >> 7, c = idx & 127;
    float v = emb[z[n] * HID + c];
    g_h[idx] = v;
    g_hb[idx] = __float2bfloat16(v);
}

__global__ void tableH_kernel(const float* __restrict__ Wf1, const float* __restrict__ bf1) {
    int inter = blockIdx.y;
    int tbase = blockIdx.x * 8;
    __shared__ float W1s[NGAUSS * HID];
    __shared__ float eas[8][NGAUSS];
    const float* W1 = Wf1 + inter * NGAUSS * HID;
    for (int i = threadIdx.x; i < NGAUSS * HID; i += 128) W1s[i] = W1[i];
    for (int i = threadIdx.x; i < 8 * NGAUSS; i += 128) {
        int r = i / NGAUSS, k = i % NGAUSS;
        float dt = (tbase + r) * DELTA;
        float u = dt - k * GSPACE;
        eas[r][k] = expf(GCOEFF * u * u);
    }
    __syncthreads();
    float b = bf1[inter * HID + threadIdx.x];
#pragma unroll
    for (int r = 0; r < 8; r++) {
        float s = b;
#pragma unroll
        for (int k = 0; k < NGAUSS; k++) s += eas[r][k] * W1s[k * HID + threadIdx.x];
        g_Hb[(size_t)(inter * NTAB + tbase + r) * HID + threadIdx.x] = __float2bfloat16(sspf(s));
    }
}

// ---------------- MMA helpers ----------------
#define MMA16816(d, a, b0, b1) \
    asm volatile("mma.sync.aligned.m16n8k16.row.col.f32.bf16.bf16.f32 " \
        "{%0,%1,%2,%3}, {%4,%5,%6,%7}, {%8,%9}, {%0,%1,%2,%3};" \
        : "+f"((d)[0]), "+f"((d)[1]), "+f"((d)[2]), "+f"((d)[3]) \
        : "r"((a)[0]), "r"((a)[1]), "r"((a)[2]), "r"((a)[3]), "r"(b0), "r"(b1))

// ---------------- standalone GEMM (first x, filter tables) ----------------
#define MODE_PLAIN 0
#define MODE_FILT  3

template <int MODE>
__global__ __launch_bounds__(256) void gemm_mma(
    const __nv_bfloat16* __restrict__ A, const float* __restrict__ W,
    const float* __restrict__ bias,
    __nv_bfloat16* __restrict__ outB,
    size_t aStride, size_t wStride, size_t bStride, size_t oStride)
{
    __shared__ __nv_bfloat16 sBhi[128][72];
    __shared__ __nv_bfloat16 sBlo[128][72];

    A += (size_t)blockIdx.y * aStride;
    W += (size_t)blockIdx.y * wStride;
    if (bias) bias += (size_t)blockIdx.y * bStride;
    outB += (size_t)blockIdx.y * oStride;

    const int tid = threadIdx.x;
    const int w = tid >> 5, lane = tid & 31;
    const int wm = w >> 1, wn = w & 1;
    const int g = lane >> 2, tg = lane & 3;
    const int row0 = blockIdx.x * 128;

    float acc[2][8][4] = {};
    const __nv_bfloat16* aBase = A + (size_t)(row0 + wm * 32 + g) * 128;

    for (int kh = 0; kh < 2; kh++) {
        __syncthreads();
        for (int idx = tid; idx < 64 * 128; idx += 256) {
            int kp = idx >> 7, n = idx & 127;
            float v = W[(size_t)(kh * 64 + kp) * 128 + n];
            __nv_bfloat16 h = __float2bfloat16(v);
            sBhi[n][kp] = h;
            sBlo[n][kp] = __float2bfloat16(v - __bfloat162float(h));
        }
        __syncthreads();

#pragma unroll
        for (int ks = 0; ks < 4; ks++) {
            int kc = kh * 64 + ks * 16 + tg * 2;
            uint32_t af[2][4];
#pragma unroll
            for (int mt = 0; mt < 2; mt++) {
                const __nv_bfloat16* rp = aBase + (size_t)mt * 16 * 128;
                af[mt][0] = *(const uint32_t*)(rp + kc);
                af[mt][1] = *(const uint32_t*)(rp + 8 * 128 + kc);
                af[mt][2] = *(const uint32_t*)(rp + kc + 8);
                af[mt][3] = *(const uint32_t*)(rp + 8 * 128 + kc + 8);
            }
            int c = ks * 16 + tg * 2;
#pragma unroll
            for (int nt = 0; nt < 8; nt++) {
                int n = wn * 64 + nt * 8 + g;
                uint32_t bh0 = *(const uint32_t*)&sBhi[n][c];
                uint32_t bh1 = *(const uint32_t*)&sBhi[n][c + 8];
                uint32_t bl0 = *(const uint32_t*)&sBlo[n][c];
                uint32_t bl1 = *(const uint32_t*)&sBlo[n][c + 8];
#pragma unroll
                for (int mt = 0; mt < 2; mt++) {
                    MMA16816(acc[mt][nt], af[mt], bh0, bh1);
                    MMA16816(acc[mt][nt], af[mt], bl0, bl1);
                }
            }
        }
    }

#pragma unroll
    for (int mt = 0; mt < 2; mt++) {
        int r0 = row0 + wm * 32 + mt * 16 + g;
        int r1 = r0 + 8;
        float s0 = 1.0f, s1 = 1.0f;
        if (MODE == MODE_FILT) {
            s0 = 0.5f * (cosf((float)r0 * DELTA * PI_O10) + 1.0f);
            s1 = 0.5f * (cosf((float)r1 * DELTA * PI_O10) + 1.0f);
        }
#pragma unroll
        for (int nt = 0; nt < 8; nt++) {
            int cc = wn * 64 + nt * 8 + tg * 2;
            float vx0 = acc[mt][nt][0], vy0 = acc[mt][nt][1];
            float vx1 = acc[mt][nt][2], vy1 = acc[mt][nt][3];
            if (MODE == MODE_FILT) {
                float2 bv = *(const float2*)(bias + cc);
                vx0 = (vx0 + bv.x) * s0; vy0 = (vy0 + bv.y) * s0;
                vx1 = (vx1 + bv.x) * s1; vy1 = (vy1 + bv.y) * s1;
            }
            *(__nv_bfloat162*)(outB + (size_t)r0 * 128 + cc) = __floats2bfloat162_rn(vx0, vy0);
            *(__nv_bfloat162*)(outB + (size_t)r1 * 128 + cc) = __floats2bfloat162_rn(vx1, vy1);
        }
    }
}

// ---------------- pipelined fused-update helpers ----------------
// Weight chunk = 64 K-rows x NC cols, staged as hi/lo bf16 [n][72].
template <int NC>
__device__ __forceinline__ void ldg_chunk(const float* __restrict__ W, int kh,
                                          float* wreg, int tid) {
#pragma unroll
    for (int i = 0; i < 64 * NC / 256; i++) {
        int flat = tid + i * 256;
        int kp = flat / NC, n = flat % NC;
        wreg[i] = W[(size_t)(kh * 64 + kp) * NC + n];
    }
}
template <int NC>
__device__ __forceinline__ void sts_chunk(const float* wreg,
                                          __nv_bfloat16* hi, __nv_bfloat16* lo, int tid) {
#pragma unroll
    for (int i = 0; i < 64 * NC / 256; i++) {
        int flat = tid + i * 256;
        int kp = flat / NC, n = flat % NC;
        float v = wreg[i];
        __nv_bfloat16 h = __float2bfloat16(v);
        hi[n * 72 + kp] = h;
        lo[n * 72 + kp] = __float2bfloat16(v - __bfloat162float(h));
    }
}

// acc += A(this warp's 32 rows, K-half kh) @ Wchunk(hi+lo)
template <int NT>
__device__ __forceinline__ void mma_half(
    const __nv_bfloat16* __restrict__ A, int lda, int kh,
    const __nv_bfloat16* hi, const __nv_bfloat16* lo,
    int wm, int wn, int g, int tg, float acc[2][NT][4])
{
    const __nv_bfloat16* rp0 = A + (wm * 32 + g) * lda;
    const int colbase = wn * (NT * 8);
#pragma unroll
    for (int ks = 0; ks < 4; ks++) {
        int kc = kh * 64 + ks * 16 + tg * 2;
        uint32_t af[2][4];
#pragma unroll
        for (int mt = 0; mt < 2; mt++) {
            const __nv_bfloat16* rp = rp0 + mt * 16 * lda;
            af[mt][0] = *(const uint32_t*)(rp + kc);
            af[mt][1] = *(const uint32_t*)(rp + 8 * lda + kc);
            af[mt][2] = *(const uint32_t*)(rp + kc + 8);
            af[mt][3] = *(const uint32_t*)(rp + 8 * lda + kc + 8);
        }
        int c = ks * 16 + tg * 2;
#pragma unroll
        for (int nt = 0; nt < NT; nt++) {
            int n = colbase + nt * 8 + g;
            uint32_t bh0 = *(const uint32_t*)(hi + n * 72 + c);
            uint32_t bh1 = *(const uint32_t*)(hi + n * 72 + c + 8);
            uint32_t bl0 = *(const uint32_t*)(lo + n * 72 + c);
            uint32_t bl1 = *(const uint32_t*)(lo + n * 72 + c + 8);
#pragma unroll
            for (int mt = 0; mt < 2; mt++) {
                MMA16816(acc[mt][nt], af[mt], bh0, bh1);
                MMA16816(acc[mt][nt], af[mt], bl0, bl1);
            }
        }
    }
}

// ---------------- fused interaction update: 3 chained GEMMs, pipelined weights ----------------
template <bool LAST>
__global__ __launch_bounds__(256) void fused_update(
    const __nv_bfloat16* __restrict__ aggb,
    float* __restrict__ h,
    const float* __restrict__ Wl2, const float* __restrict__ bl2,
    const float* __restrict__ Wl,  const float* __restrict__ bl,
    const float* __restrict__ W3,
    const float* __restrict__ bo1, const float* __restrict__ Wo2,
    __nv_bfloat16* __restrict__ xb)
{
    extern __shared__ __align__(16) char smem_raw[];
    __nv_bfloat16* sWhi0 = (__nv_bfloat16*)smem_raw;     // 128*72
    __nv_bfloat16* sWlo0 = sWhi0 + 128 * 72;
    __nv_bfloat16* sWhi1 = sWlo0 + 128 * 72;
    __nv_bfloat16* sWlo1 = sWhi1 + 128 * 72;
    __nv_bfloat16* sT    = sWlo1 + 128 * 72;             // 128*136
    __nv_bfloat16* sHn   = sT + 128 * 136;               // 128*136

    const int tid = threadIdx.x;
    const int w = tid >> 5, lane = tid & 31;
    const int wm = w >> 1, wn = w & 1;
    const int g = lane >> 2, tg = lane & 3;
    const int row0 = blockIdx.x * 128;

    float wreg[32];
    const __nv_bfloat16* aggA = aggb + (size_t)row0 * 128;

    // preload (Wl2, kh0)
    ldg_chunk<128>(Wl2, 0, wreg, tid);
    sts_chunk<128>(wreg, sWhi0, sWlo0, tid);
    __syncthreads();

    // ======== stage 1: t = ssp(aggb @ Wl2 + bl2) ========
    float acc1[2][8][4] = {};
    ldg_chunk<128>(Wl2, 1, wreg, tid);
    mma_half<8>(aggA, 128, 0, sWhi0, sWlo0, wm, wn, g, tg, acc1);
    sts_chunk<128>(wreg, sWhi1, sWlo1, tid);
    __syncthreads();

    ldg_chunk<128>(Wl, 0, wreg, tid);
    mma_half<8>(aggA, 128, 1, sWhi1, sWlo1, wm, wn, g, tg, acc1);
    sts_chunk<128>(wreg, sWhi0, sWlo0, tid);
    {
#pragma unroll
        for (int mt = 0; mt < 2; mt++) {
            int r0 = wm * 32 + mt * 16 + g;
            int r1 = r0 + 8;
#pragma unroll
            for (int nt = 0; nt < 8; nt++) {
                int cc = wn * 64 + nt * 8 + tg * 2;
                float2 bv = *(const float2*)(bl2 + cc);
                float vx0 = sspf(acc1[mt][nt][0] + bv.x);
                float vy0 = sspf(acc1[mt][nt][1] + bv.y);
                float vx1 = sspf(acc1[mt][nt][2] + bv.x);
                float vy1 = sspf(acc1[mt][nt][3] + bv.y);
                *(__nv_bfloat162*)(sT + r0 * 136 + cc) = __floats2bfloat162_rn(vx0, vy0);
                *(__nv_bfloat162*)(sT + r1 * 136 + cc) = __floats2bfloat162_rn(vx1, vy1);
            }
        }
    }
    __syncthreads();

    // ======== stage 2: hn = t @ Wl + bl + h ========
    float acc2[2][8][4] = {};
    ldg_chunk<128>(Wl, 1, wreg, tid);
    mma_half<8>(sT, 136, 0, sWhi0, sWlo0, wm, wn, g, tg, acc2);
    sts_chunk<128>(wreg, sWhi1, sWlo1, tid);
    __syncthreads();

    if (!LAST) ldg_chunk<128>(W3, 0, wreg, tid);
    else       ldg_chunk<64>(W3, 0, wreg, tid);
    mma_half<8>(sT, 136, 1, sWhi1, sWlo1, wm, wn, g, tg, acc2);
    if (!LAST) sts_chunk<128>(wreg, sWhi0, sWlo0, tid);
    else       sts_chunk<64>(wreg, sWhi0, sWlo0, tid);
    {
#pragma unroll
        for (int mt = 0; mt < 2; mt++) {
            int r0 = wm * 32 + mt * 16 + g;
            int r1 = r0 + 8;
            float* h0p = h + (size_t)(row0 + r0) * 128;
            float* h1p = h + (size_t)(row0 + r1) * 128;
#pragma unroll
            for (int nt = 0; nt < 8; nt++) {
                int cc = wn * 64 + nt * 8 + tg * 2;
                float2 bv = *(const float2*)(bl + cc);
                float2 e0 = *(const float2*)(h0p + cc);
                float2 e1 = *(const float2*)(h1p + cc);
                float vx0 = acc2[mt][nt][0] + bv.x + e0.x;
                float vy0 = acc2[mt][nt][1] + bv.y + e0.y;
                float vx1 = acc2[mt][nt][2] + bv.x + e1.x;
                float vy1 = acc2[mt][nt][3] + bv.y + e1.y;
                *(float2*)(h0p + cc) = make_float2(vx0, vy0);
                *(float2*)(h1p + cc) = make_float2(vx1, vy1);
                *(__nv_bfloat162*)(sHn + r0 * 136 + cc) = __floats2bfloat162_rn(vx0, vy0);
                *(__nv_bfloat162*)(sHn + r1 * 136 + cc) = __floats2bfloat162_rn(vx1, vy1);
            }
        }
    }
    __syncthreads();

    // ======== stage 3: next x or readout ========
    if (!LAST) {
        float acc3[2][8][4] = {};
        ldg_chunk<128>(W3, 1, wreg, tid);
        mma_half<8>(sHn, 136, 0, sWhi0, sWlo0, wm, wn, g, tg, acc3);
        sts_chunk<128>(wreg, sWhi1, sWlo1, tid);
        __syncthreads();
        mma_half<8>(sHn, 136, 1, sWhi1, sWlo1, wm, wn, g, tg, acc3);
#pragma unroll
        for (int mt = 0; mt < 2; mt++) {
            int r0 = row0 + wm * 32 + mt * 16 + g;
            int r1 = r0 + 8;
#pragma unroll
            for (int nt = 0; nt < 8; nt++) {
                int cc = wn * 64 + nt * 8 + tg * 2;
                *(__nv_bfloat162*)(xb + (size_t)r0 * 128 + cc) =
                    __floats2bfloat162_rn(acc3[mt][nt][0], acc3[mt][nt][1]);
                *(__nv_bfloat162*)(xb + (size_t)r1 * 128 + cc) =
                    __floats2bfloat162_rn(acc3[mt][nt][2], acc3[mt][nt][3]);
            }
        }
    } else {
        float acc3[2][4][4] = {};
        ldg_chunk<64>(W3, 1, wreg, tid);
        mma_half<4>(sHn, 136, 0, sWhi0, sWlo0, wm, wn, g, tg, acc3);
        sts_chunk<64>(wreg, sWhi1, sWlo1, tid);
        __syncthreads();
        mma_half<4>(sHn, 136, 1, sWhi1, sWlo1, wm, wn, g, tg, acc3);
        float v = 0.0f;
#pragma unroll
        for (int mt = 0; mt < 2; mt++) {
#pragma unroll
            for (int nt = 0; nt < 4; nt++) {
                int cc = wn * 32 + nt * 8 + tg * 2;
                float2 bo = *(const float2*)(bo1 + cc);
                float2 w2 = *(const float2*)(Wo2 + cc);
                v += sspf(acc3[mt][nt][0] + bo.x) * w2.x + sspf(acc3[mt][nt][1] + bo.y) * w2.y;
                v += sspf(acc3[mt][nt][2] + bo.x) * w2.x + sspf(acc3[mt][nt][3] + bo.y) * w2.y;
            }
        }
#pragma unroll
        for (int off = 16; off > 0; off >>= 1)
            v += __shfl_xor_sync(0xFFFFFFFFu, v, off);
        if (lane == 0) atomicAdd(&g_sum, v);
    }
}

// ---------------- edge aggregation (dst-sorted, warp/node, lerp table) ----------------
__device__ __forceinline__ void edge_acc(const __nv_bfloat16* xb, const __nv_bfloat16* Tb,
                                         int pk, float wt, int lane, float4& acc) {
    int s = pk & 0xFFFF;
    int t0 = pk >> 16;
    uint2 xv = ((const uint2*)(xb + (size_t)s * 128))[lane];
    uint2 a0 = ((const uint2*)(Tb + (size_t)t0 * 128))[lane];
    uint2 a1 = ((const uint2*)(Tb + (size_t)(t0 + 1) * 128))[lane];
    float2 x0 = __bfloat1622float2(*(__nv_bfloat162*)&xv.x);
    float2 x1 = __bfloat1622float2(*(__nv_bfloat162*)&xv.y);
    float2 p0 = __bfloat1622float2(*(__nv_bfloat162*)&a0.x);
    float2 p1 = __bfloat1622float2(*(__nv_bfloat162*)&a0.y);
    float2 q0 = __bfloat1622float2(*(__nv_bfloat162*)&a1.x);
    float2 q1 = __bfloat1622float2(*(__nv_bfloat162*)&a1.y);
    float w0 = 1.0f - wt;
    acc.x += x0.x * (w0 * p0.x + wt * q0.x);
    acc.y += x0.y * (w0 * p0.y + wt * q0.y);
    acc.z += x1.x * (w0 * p1.x + wt * q1.x);
    acc.w += x1.y * (w0 * p1.y + wt * q1.y);
}

__global__ void agg_kernel(const __nv_bfloat16* __restrict__ xb,
                           const __nv_bfloat16* __restrict__ Tb) {
    int warp = (blockIdx.x * blockDim.x + threadIdx.x) >> 5;
    int lane = threadIdx.x & 31;
    if (warp >= NN) return;
    int b = g_start[warp];
    int e = g_start[warp + 1];
    float4 acc = make_float4(0.f, 0.f, 0.f, 0.f);
    int j = b;
    for (; j + 2 <= e; j += 2) {
        int pk0 = g_perm[j], pk1 = g_perm[j + 1];
        float w0 = g_pw[j], w1 = g_pw[j + 1];
        edge_acc(xb, Tb, pk0, w0, lane, acc);
        edge_acc(xb, Tb, pk1, w1, lane, acc);
    }
    if (j < e) edge_acc(xb, Tb, g_perm[j], g_pw[j], lane, acc);
    __nv_bfloat162 o0 = __floats2bfloat162_rn(acc.x, acc.y);
    __nv_bfloat162 o1 = __floats2bfloat162_rn(acc.z, acc.w);
    uint2 ov;
    ov.x = *(uint32_t*)&o0;
    ov.y = *(uint32_t*)&o1;
    ((uint2*)(g_aggb + (size_t)warp * 128))[lane] = ov;
}

__global__ void final_kernel(float* __restrict__ out, const float* __restrict__ bo2) {
    float v = g_sum + (float)NN * bo2[0];
    out[0] = fmaxf(v, 0.0f);
}

// ---------------- launch ----------------
extern "C" void kernel_launch(void* const* d_in, const int* in_sizes, int n_in,
                              void* d_out, int out_size) {
    const int*   z    = (const int*)d_in[0];
    const float* pos  = (const float*)d_in[1];
    const int*   ei   = (const int*)d_in[2];
    const float* emb  = (const float*)d_in[3];
    const float* Wf1  = (const float*)d_in[4];
    const float* bf1  = (const float*)d_in[5];
    const float* Wf2  = (const float*)d_in[6];
    const float* bf2  = (const float*)d_in[7];
    const float* Wl1  = (const float*)d_in[8];
    const float* Wl2  = (const float*)d_in[9];
    const float* bl2  = (const float*)d_in[10];
    const float* Wl   = (const float*)d_in[11];
    const float* bl   = (const float*)d_in[12];
    const float* Wo1  = (const float*)d_in[13];
    const float* bo1  = (const float*)d_in[14];
    const float* Wo2  = (const float*)d_in[15];
    const float* bo2  = (const float*)d_in[16];
    float* out = (float*)d_out;

    float *p_h;
    __nv_bfloat16 *p_hb, *p_xb, *p_aggb, *p_Hb, *p_Tb;
    cudaGetSymbolAddress((void**)&p_h,    g_h);
    cudaGetSymbolAddress((void**)&p_hb,   g_hb);
    cudaGetSymbolAddress((void**)&p_xb,   g_xb);
    cudaGetSymbolAddress((void**)&p_aggb, g_aggb);
    cudaGetSymbolAddress((void**)&p_Hb,   g_Hb);
    cudaGetSymbolAddress((void**)&p_Tb,   g_Tb);

    const int FUSED_SMEM = (4 * 128 * 72 + 2 * 128 * 136) * (int)sizeof(__nv_bfloat16);
    cudaFuncSetAttribute(fused_update<false>, cudaFuncAttributeMaxDynamicSharedMemorySize, FUSED_SMEM);
    cudaFuncSetAttribute(fused_update<true>,  cudaFuncAttributeMaxDynamicSharedMemorySize, FUSED_SMEM);

    // --- edge prep + dst sort ---
    zero_kernel<<<NN / 256, 256>>>();
    prep_kernel<<<EE / 256, 256>>>(pos, ei);
    scan_kernel<<<1, 1024>>>();
    scatter_kernel<<<EE / 256, 256>>>(ei);
    emb_kernel<<<NN * HID / 256, 256>>>(z, emb);

    // --- filter tables (batched over all 6 interactions) ---
    tableH_kernel<<<dim3(NTAB / 8, NINTER), 128>>>(Wf1, bf1);
    gemm_mma<MODE_FILT><<<dim3(NTAB / 128, NINTER), 256>>>(
        p_Hb, Wf2, bf2, p_Tb,
        (size_t)NTAB * HID, (size_t)HID * HID, (size_t)HID, (size_t)NTAB * HID);

    // --- first x = h @ Wl1[0] ---
    gemm_mma<MODE_PLAIN><<<NN / 128, 256>>>(p_hb, Wl1, nullptr, p_xb, 0, 0, 0, 0);

    // --- interaction blocks: agg + fused pipelined update ---
    for (int i = 0; i < NINTER; i++) {
        agg_kernel<<<NN / 8, 256>>>(p_xb, p_Tb + (size_t)i * NTAB * HID);
        if (i < NINTER - 1) {
            fused_update<false><<<NN / 128, 256, FUSED_SMEM>>>(
                p_aggb, p_h,
                Wl2 + (size_t)i * HID * HID, bl2 + (size_t)i * HID,
                Wl  + (size_t)i * HID * HID, bl  + (size_t)i * HID,
                Wl1 + (size_t)(i + 1) * HID * HID, nullptr, nullptr, p_xb);
        } else {
            fused_update<true><<<NN / 128, 256, FUSED_SMEM>>>(
                p_aggb, p_h,
                Wl2 + (size_t)i * HID * HID, bl2 + (size_t)i * HID,
                Wl  + (size_t)i * HID * HID, bl  + (size_t)i * HID,
                Wo1, bo1, Wo2, nullptr);
        }
    }

    final_kernel<<<1, 1>>>(out, bo2);
}